// round 15
// baseline (speedup 1.0000x reference)
#include <cuda_runtime.h>
#include <cuda_bf16.h>

#define MAXN 50000
#define MAXE 1000000
#define C 64

// ---------------- device scratch ----------------
__device__ __align__(16) float d_tmp[MAXN * C];   // pre-agg h; reused as A in MLP stage
__device__ __align__(16) float d_h[MAXN * C];     // layer output (relu'd)
__device__ __align__(16) float d_B[MAXN * C];     // h@Wm1_bot
__device__ float d_al[MAXN];
__device__ float d_ar[MAXN];
__device__ float d_p[MAXN];      // self dot h.h (fused into gemm epilogue)
__device__ int   d_cnt[MAXN];    // statically zero; re-zeroed by scatter_zero each replay
__device__ int   d_cur[MAXN];
__device__ int   d_rp[MAXN + 1];
__device__ __align__(16) int4 d_pk[MAXE];  // packed CSR entry: {src, eid, att_bits, 0}
__device__ unsigned d_stat[64];  // lookback statuses (flag in bits 30-31)

// ---------------- CSR build ----------------
__global__ void count_k(const int* __restrict__ ei, int E) {
    if (blockIdx.x == 0 && threadIdx.x < 64) d_stat[threadIdx.x] = 0u;
    int e = blockIdx.x * blockDim.x + threadIdx.x;
    if (e < E) atomicAdd(&d_cnt[ei[E + e]], 1);
}

// single-pass scan with decoupled lookback (grid <= 64 blocks, single wave)
__global__ void scan_fused(int n, int E) {
    cudaGridDependencySynchronize();   // wait for count_k's d_cnt
    __shared__ int wsum[32];
    __shared__ int s_prev;
    int tid = threadIdx.x, lane = tid & 31, w = tid >> 5;
    int i = blockIdx.x * 1024 + tid;
    int v = (i < n) ? d_cnt[i] : 0;
    int x = v;
    #pragma unroll
    for (int o = 1; o < 32; o <<= 1) {
        int t = __shfl_up_sync(~0u, x, o);
        if (lane >= o) x += t;
    }
    if (lane == 31) wsum[w] = x;
    __syncthreads();
    if (w == 0) {
        int y = wsum[lane];
        #pragma unroll
        for (int o = 1; o < 32; o <<= 1) {
            int t = __shfl_up_sync(~0u, y, o);
            if (lane >= o) y += t;
        }
        wsum[lane] = y;
    }
    __syncthreads();
    int incl = x + (w > 0 ? wsum[w - 1] : 0);
    unsigned total = (unsigned)wsum[31];

    if (tid == 0) {
        int bid = blockIdx.x;
        if (bid == 0) {
            atomicExch(&d_stat[0], (2u << 30) | total);
            s_prev = 0;
        } else {
            atomicExch(&d_stat[bid], (1u << 30) | total);
            unsigned prev = 0;
            for (int j = bid - 1; j >= 0; j--) {
                unsigned st;
                do { st = atomicAdd(&d_stat[j], 0u); } while ((st >> 30) == 0u);
                prev += st & 0x3FFFFFFFu;
                if ((st >> 30) == 2u) break;
            }
            atomicExch(&d_stat[bid], (2u << 30) | (prev + total));
            s_prev = (int)prev;
        }
    }
    __syncthreads();
    int base = s_prev;
    if (i < n) {
        int val = incl - v + base;
        d_rp[i] = val;
        d_cur[i] = val;
    }
    if (i == 0) d_rp[n] = E;
}

// scatter into packed CSR (ONE 16B store per edge); re-zero d_cnt for next replay
__global__ void scatter_zero(const int* __restrict__ ei, const float* __restrict__ eattr,
                             int E, int n) {
    int e = blockIdx.x * blockDim.x + threadIdx.x;
    // prologue: input-only loads before the dependency sync
    int src = 0, dst = 0; float at = 0.f;
    if (e < E) {
        src = ei[e];
        dst = ei[E + e];
        at = eattr[e];
    }
    cudaGridDependencySynchronize();   // wait for scan's d_cur
    if (e < n) d_cnt[e] = 0;
    if (e < E) {
        int pos = atomicAdd(&d_cur[dst], 1);
        int4 val;
        val.x = src;
        val.y = e;
        val.z = __float_as_int(at);
        val.w = 0;
        d_pk[pos] = val;
    }
}

// ---------------- register-blocked GEMM (sX[64][65], scalar X reads) ----------------
template <bool DEP_SYNC>
__device__ __forceinline__ void gemm64r_att_body(const float* __restrict__ X,
                                                 const float* __restrict__ W,
                                                 const float* __restrict__ attl,
                                                 const float* __restrict__ attr_, int n) {
    __shared__ float sX[64][65];
    __shared__ float sW[64 * 64];
    int tid = threadIdx.x;  // 256
    int row0 = blockIdx.x * 64;
    #pragma unroll
    for (int i = 0; i < 4; i++)
        ((float4*)sW)[tid + 256 * i] = ((const float4*)W)[tid + 256 * i];
    if (DEP_SYNC) cudaGridDependencySynchronize();
    #pragma unroll
    for (int i = 0; i < 4; i++) {
        int idx = tid + 256 * i;
        int r = idx >> 4, c4 = (idx & 15) * 4;
        int gr = row0 + r;
        float4 xv = (gr < n) ? *(const float4*)&X[gr * 64 + c4]
                             : make_float4(0.f, 0.f, 0.f, 0.f);
        sX[r][c4] = xv.x; sX[r][c4 + 1] = xv.y; sX[r][c4 + 2] = xv.z; sX[r][c4 + 3] = xv.w;
    }
    __syncthreads();
    int tx = tid & 15, ty = tid >> 4;
    int rb = ty * 4, cb = tx * 4;
    float4 ac[4] = {{0,0,0,0},{0,0,0,0},{0,0,0,0},{0,0,0,0}};
    #pragma unroll
    for (int k = 0; k < 64; k++) {
        float4 wv = *(const float4*)&sW[k * 64 + cb];
        float x0 = sX[rb][k], x1 = sX[rb + 1][k], x2 = sX[rb + 2][k], x3 = sX[rb + 3][k];
        ac[0].x += x0 * wv.x; ac[0].y += x0 * wv.y; ac[0].z += x0 * wv.z; ac[0].w += x0 * wv.w;
        ac[1].x += x1 * wv.x; ac[1].y += x1 * wv.y; ac[1].z += x1 * wv.z; ac[1].w += x1 * wv.w;
        ac[2].x += x2 * wv.x; ac[2].y += x2 * wv.y; ac[2].z += x2 * wv.z; ac[2].w += x2 * wv.w;
        ac[3].x += x3 * wv.x; ac[3].y += x3 * wv.y; ac[3].z += x3 * wv.z; ac[3].w += x3 * wv.w;
    }
    float4 l4 = *(const float4*)&attl[cb];
    float4 r4 = *(const float4*)&attr_[cb];
    float la[4], ra[4], pp[4];
    #pragma unroll
    for (int i = 0; i < 4; i++) {
        la[i] = ac[i].x * l4.x + ac[i].y * l4.y + ac[i].z * l4.z + ac[i].w * l4.w;
        ra[i] = ac[i].x * r4.x + ac[i].y * r4.y + ac[i].z * r4.z + ac[i].w * r4.w;
        pp[i] = ac[i].x * ac[i].x + ac[i].y * ac[i].y + ac[i].z * ac[i].z + ac[i].w * ac[i].w;
    }
    #pragma unroll
    for (int o = 8; o; o >>= 1) {
        #pragma unroll
        for (int i = 0; i < 4; i++) {
            la[i] += __shfl_xor_sync(~0u, la[i], o);
            ra[i] += __shfl_xor_sync(~0u, ra[i], o);
            pp[i] += __shfl_xor_sync(~0u, pp[i], o);
        }
    }
    #pragma unroll
    for (int i = 0; i < 4; i++) {
        int gr = row0 + rb + i;
        if (gr < n) {
            *(float4*)&d_tmp[gr * 64 + cb] = ac[i];
            if (tx == 0) { d_al[gr] = la[i]; d_ar[gr] = ra[i]; d_p[gr] = pp[i]; }
        }
    }
}

__global__ void gemm64r_att_x(const float* __restrict__ X, const float* __restrict__ W,
                              const float* __restrict__ attl, const float* __restrict__ attr_, int n) {
    gemm64r_att_body<false>(X, W, attl, attr_, n);
}
__global__ void gemm64r_att_h(const float* __restrict__ W,
                              const float* __restrict__ attl, const float* __restrict__ attr_, int n) {
    gemm64r_att_body<true>(d_h, W, attl, attr_, n);
}

// fused: A = h@W_top -> d_tmp, B = h@W_bot -> d_B
__global__ void gemm64r_mlp2(const float* __restrict__ Wtop, const float* __restrict__ Wbot, int n) {
    __shared__ float sX[64][65];
    __shared__ float sW1[64 * 64];
    __shared__ float sW2[64 * 64];
    int tid = threadIdx.x;
    int row0 = blockIdx.x * 64;
    #pragma unroll
    for (int i = 0; i < 4; i++) {
        ((float4*)sW1)[tid + 256 * i] = ((const float4*)Wtop)[tid + 256 * i];
        ((float4*)sW2)[tid + 256 * i] = ((const float4*)Wbot)[tid + 256 * i];
    }
    cudaGridDependencySynchronize();   // wait for agg2's d_h
    #pragma unroll
    for (int i = 0; i < 4; i++) {
        int idx = tid + 256 * i;
        int r = idx >> 4, c4 = (idx & 15) * 4;
        int gr = row0 + r;
        float4 xv = (gr < n) ? *(const float4*)&d_h[gr * 64 + c4]
                             : make_float4(0.f, 0.f, 0.f, 0.f);
        sX[r][c4] = xv.x; sX[r][c4 + 1] = xv.y; sX[r][c4 + 2] = xv.z; sX[r][c4 + 3] = xv.w;
    }
    __syncthreads();
    int tx = tid & 15, ty = tid >> 4;
    int rb = ty * 4, cb = tx * 4;
    float4 a[4] = {{0,0,0,0},{0,0,0,0},{0,0,0,0},{0,0,0,0}};
    float4 b[4] = {{0,0,0,0},{0,0,0,0},{0,0,0,0},{0,0,0,0}};
    #pragma unroll
    for (int k = 0; k < 64; k++) {
        float4 w1 = *(const float4*)&sW1[k * 64 + cb];
        float4 w2 = *(const float4*)&sW2[k * 64 + cb];
        float x0 = sX[rb][k], x1 = sX[rb + 1][k], x2 = sX[rb + 2][k], x3 = sX[rb + 3][k];
        a[0].x += x0 * w1.x; a[0].y += x0 * w1.y; a[0].z += x0 * w1.z; a[0].w += x0 * w1.w;
        a[1].x += x1 * w1.x; a[1].y += x1 * w1.y; a[1].z += x1 * w1.z; a[1].w += x1 * w1.w;
        a[2].x += x2 * w1.x; a[2].y += x2 * w1.y; a[2].z += x2 * w1.z; a[2].w += x2 * w1.w;
        a[3].x += x3 * w1.x; a[3].y += x3 * w1.y; a[3].z += x3 * w1.z; a[3].w += x3 * w1.w;
        b[0].x += x0 * w2.x; b[0].y += x0 * w2.y; b[0].z += x0 * w2.z; b[0].w += x0 * w2.w;
        b[1].x += x1 * w2.x; b[1].y += x1 * w2.y; b[1].z += x1 * w2.z; b[1].w += x1 * w2.w;
        b[2].x += x2 * w2.x; b[2].y += x2 * w2.y; b[2].z += x2 * w2.z; b[2].w += x2 * w2.w;
        b[3].x += x3 * w2.x; b[3].y += x3 * w2.y; b[3].z += x3 * w2.z; b[3].w += x3 * w2.w;
    }
    #pragma unroll
    for (int i = 0; i < 4; i++) {
        int gr = row0 + rb + i;
        if (gr < n) {
            *(float4*)&d_tmp[gr * 64 + cb] = a[i];
            *(float4*)&d_B[gr * 64 + cb] = b[i];
        }
    }
}

// sigmoid via MUFU.TANH
__device__ __forceinline__ float lrelu_sig(float base, float q) {
    float t;
    asm("tanh.approx.f32 %0, %1;" : "=f"(t) : "f"(q * 0.5f));
    float a = base * (0.5f * t + 0.5f);
    return fmaxf(a, 0.2f * a);
}

// ---------------- half-warp aggregation, direct exp-sum, id-prefetch pipeline ----------------
__global__ void aggregate2(const float* __restrict__ bias, int n) {
    int lane = threadIdx.x & 31;
    int half = lane >> 4, l = lane & 15;
    float4 bv = ((const float4*)bias)[l];
    cudaGridDependencySynchronize();
    int gw = (blockIdx.x * blockDim.x + threadIdx.x) >> 5;
    int node = gw * 2 + half;
    if (node >= n) return;
    unsigned mk = 0xFFFFu << (half * 16);
    const float4* h4 = (const float4*)d_tmp;
    float4 hd = h4[node * 16 + l];
    float ar_i = d_ar[node];

    float e_self = __expf(lrelu_sig(d_al[node] + ar_i, d_p[node]));
    float s = e_self;
    float4 acc = make_float4(e_self * hd.x, e_self * hd.y, e_self * hd.z, e_self * hd.w);

    int beg = d_rp[node], end = d_rp[node + 1];
    int id[8], id_n[8];
    // preload first batch ids
    #pragma unroll
    for (int i = 0; i < 8; i++) id[i] = (beg + i < end) ? d_pk[beg + i].x : ((beg < end) ? d_pk[beg].x : 0);
    for (int k = beg; k < end; k += 8) {
        // prefetch next batch ids while this batch computes
        int kn = k + 8;
        if (kn < end) {
            #pragma unroll
            for (int i = 0; i < 8; i++) id_n[i] = (kn + i < end) ? d_pk[kn + i].x : d_pk[kn].x;
        }
        float4 v[8];
        float q[8];
        #pragma unroll
        for (int i = 0; i < 8; i++) v[i] = h4[id[i] * 16 + l];
        #pragma unroll
        for (int i = 0; i < 8; i++)
            q[i] = hd.x * v[i].x + hd.y * v[i].y + hd.z * v[i].z + hd.w * v[i].w;
        #pragma unroll
        for (int o = 8; o; o >>= 1) {
            #pragma unroll
            for (int i = 0; i < 8; i++) q[i] += __shfl_xor_sync(mk, q[i], o);
        }
        #pragma unroll
        for (int i = 0; i < 8; i++) {
            float e = (k + i < end) ? __expf(lrelu_sig(d_al[id[i]] + ar_i, q[i])) : 0.f;
            s += e;
            acc.x += e * v[i].x; acc.y += e * v[i].y;
            acc.z += e * v[i].z; acc.w += e * v[i].w;
        }
        #pragma unroll
        for (int i = 0; i < 8; i++) id[i] = id_n[i];
    }
    float inv = __fdividef(1.f, s);
    float4 o;
    o.x = fmaxf(acc.x * inv + bv.x, 0.f);
    o.y = fmaxf(acc.y * inv + bv.y, 0.f);
    o.z = fmaxf(acc.z * inv + bv.z, 0.f);
    o.w = fmaxf(acc.w * inv + bv.w, 0.f);
    ((float4*)d_h)[node * 16 + l] = o;
}

// ---------------- edge MLP, CSR-grouped, half-warp, batch 8, pk-prefetch pipeline ----------------
__global__ void edge_mlp2(const float* __restrict__ Wm1, const float* __restrict__ bm1,
                          const float* __restrict__ Wm2, const float* __restrict__ bm2,
                          float* __restrict__ out, int n) {
    int lane = threadIdx.x & 31;
    int half = lane >> 4, l = lane & 15;
    float4 we = ((const float4*)(Wm1 + 64 * 64))[l];  // row 64 of [129,64]
    float4 bb = ((const float4*)bm1)[l];
    float4 w2 = ((const float4*)Wm2)[l];
    float b2c = bm2[0];
    cudaGridDependencySynchronize();
    int gw = (blockIdx.x * blockDim.x + threadIdx.x) >> 5;
    int node = gw * 2 + half;
    if (node >= n) return;
    unsigned mk = 0xFFFFu << (half * 16);
    float4 bd = ((const float4*)d_B)[node * 16 + l];
    bd.x += bb.x; bd.y += bb.y; bd.z += bb.z; bd.w += bb.w;
    const float4* A4 = (const float4*)d_tmp;

    int beg = d_rp[node], end = d_rp[node + 1];
    int4 pk[8], pk_n[8];
    #pragma unroll
    for (int i = 0; i < 8; i++)
        pk[i] = (beg + i < end) ? d_pk[beg + i] : ((beg < end) ? d_pk[beg] : make_int4(0, -1, 0, 0));
    for (int k = beg; k < end; k += 8) {
        int kn = k + 8;
        if (kn < end) {
            #pragma unroll
            for (int i = 0; i < 8; i++) pk_n[i] = (kn + i < end) ? d_pk[kn + i] : d_pk[kn];
        }
        float p[8];
        #pragma unroll
        for (int i = 0; i < 8; i++) {
            float4 a = A4[pk[i].x * 16 + l];
            float ti = __int_as_float(pk[i].z);
            float vx = fmaxf(a.x + bd.x + ti * we.x, 0.f);
            float vy = fmaxf(a.y + bd.y + ti * we.y, 0.f);
            float vz = fmaxf(a.z + bd.z + ti * we.z, 0.f);
            float vw = fmaxf(a.w + bd.w + ti * we.w, 0.f);
            p[i] = vx * w2.x + vy * w2.y + vz * w2.z + vw * w2.w;
        }
        #pragma unroll
        for (int o = 8; o; o >>= 1) {
            #pragma unroll
            for (int i = 0; i < 8; i++) p[i] += __shfl_xor_sync(mk, p[i], o);
        }
        if (l == 0) {
            #pragma unroll
            for (int i = 0; i < 8; i++)
                if (k + i < end && pk[i].y >= 0) out[pk[i].y] = p[i] + b2c;
        }
        #pragma unroll
        for (int i = 0; i < 8; i++) pk[i] = pk_n[i];
    }
}

// ---------------- launch helpers ----------------
template <typename F, typename... Args>
static inline void launch_pss(F kern, dim3 g, dim3 b, cudaStream_t s, Args... args) {
    cudaLaunchConfig_t cfg = {};
    cfg.gridDim = g;
    cfg.blockDim = b;
    cfg.dynamicSmemBytes = 0;
    cfg.stream = s;
    cudaLaunchAttribute attrs[1];
    attrs[0].id = cudaLaunchAttributeProgrammaticStreamSerialization;
    attrs[0].val.programmaticStreamSerializationAllowed = 1;
    cfg.attrs = attrs;
    cfg.numAttrs = 1;
    cudaLaunchKernelEx(&cfg, kern, args...);
}

// ---------------- launch ----------------
extern "C" void kernel_launch(void* const* d_in, const int* in_sizes, int n_in,
                              void* d_out, int out_size) {
    const float* x     = (const float*)d_in[0];
    const int*   ei    = (const int*)d_in[1];     // int32: JAX x64 disabled
    const float* eattr = (const float*)d_in[2];
    const float* W1    = (const float*)d_in[3];
    const float* attl1 = (const float*)d_in[4];
    const float* attr1 = (const float*)d_in[5];
    const float* b1    = (const float*)d_in[6];
    const float* W2    = (const float*)d_in[7];
    const float* attl2 = (const float*)d_in[8];
    const float* attr2 = (const float*)d_in[9];
    const float* b2    = (const float*)d_in[10];
    const float* Wm1   = (const float*)d_in[11];
    const float* bm1   = (const float*)d_in[12];
    const float* Wm2   = (const float*)d_in[13];
    const float* bm2   = (const float*)d_in[14];
    float* out = (float*)d_out;

    int N = in_sizes[0] / C;
    int E = in_sizes[2];

    int eb = (E + 255) / 256;
    int gb = (N + 63) / 64;
    int npairs = (N + 1) / 2;
    int pb = (npairs * 32 + 255) / 256;
    int sb = (N + 1023) / 1024;   // <= 64 for the lookback scan

    // side stream: overlap layer-1 GEMM (inputs only) with the CSR build
    static cudaStream_t s2 = nullptr;
    static cudaEvent_t ev_fork = nullptr, ev_join = nullptr;
    if (s2 == nullptr) {
        cudaStreamCreateWithFlags(&s2, cudaStreamNonBlocking);
        cudaEventCreateWithFlags(&ev_fork, cudaEventDisableTiming);
        cudaEventCreateWithFlags(&ev_join, cudaEventDisableTiming);
    }

    cudaEventRecord(ev_fork, 0);
    cudaStreamWaitEvent(s2, ev_fork, 0);
    gemm64r_att_x<<<gb, 256, 0, s2>>>(x, W1, attl1, attr1, N);
    cudaEventRecord(ev_join, s2);

    // CSR build on main stream (PDL-chained)
    count_k<<<eb, 256>>>(ei, E);
    launch_pss(scan_fused, dim3(sb), dim3(1024), (cudaStream_t)0, N, E);
    launch_pss(scatter_zero, dim3(eb), dim3(256), (cudaStream_t)0, ei, eattr, E, N);

    // join, then layer 1 aggregation
    cudaStreamWaitEvent(0, ev_join, 0);
    launch_pss(aggregate2, dim3(pb), dim3(256), (cudaStream_t)0, b1, N);

    // layer 2
    launch_pss(gemm64r_att_h, dim3(gb), dim3(256), (cudaStream_t)0, W2, attl2, attr2, N);
    launch_pss(aggregate2, dim3(pb), dim3(256), (cudaStream_t)0, b2, N);

    // edge MLP
    launch_pss(gemm64r_mlp2, dim3(gb), dim3(256), (cudaStream_t)0, Wm1, Wm1 + 65 * 64, N);
    launch_pss(edge_mlp2, dim3(pb), dim3(256), (cudaStream_t)0, Wm1, bm1, Wm2, bm2, out, N);
}

// round 16
// speedup vs baseline: 1.3487x; 1.3487x over previous
#include <cuda_runtime.h>
#include <cuda_bf16.h>
#include <cuda_fp16.h>

#define MAXN 50000
#define MAXE 1000000
#define C 64

// ---------------- device scratch ----------------
__device__ __align__(16) __half d_tmpH[MAXN * C]; // pre-agg h (fp16); reused as A in MLP stage
__device__ __align__(16) float  d_h[MAXN * C];    // layer output (relu'd, fp32)
__device__ __align__(16) __half d_BH[MAXN * C];   // h@Wm1_bot (fp16)
__device__ float d_al[MAXN];
__device__ float d_ar[MAXN];
__device__ float d_p[MAXN];      // self dot h.h (fused into gemm epilogue, fp32)
__device__ int   d_cnt[MAXN];    // statically zero; re-zeroed by scatter_zero each replay
__device__ int   d_cur[MAXN];
__device__ int   d_rp[MAXN + 1];
__device__ __align__(16) int4 d_pk[MAXE];  // packed CSR entry: {src, eid, att_bits, 0}
__device__ unsigned d_stat[64];  // lookback statuses (flag in bits 30-31)

// ---------------- fp16 pack/unpack helpers ----------------
__device__ __forceinline__ float4 ld_half4(const uint2* base, int idx) {
    uint2 u = base[idx];
    __half2 h0 = *reinterpret_cast<__half2*>(&u.x);
    __half2 h1 = *reinterpret_cast<__half2*>(&u.y);
    float2 f0 = __half22float2(h0);
    float2 f1 = __half22float2(h1);
    return make_float4(f0.x, f0.y, f1.x, f1.y);
}
__device__ __forceinline__ void st_half4(__half* dst, float4 v) {
    __half2 a = __floats2half2_rn(v.x, v.y);
    __half2 b = __floats2half2_rn(v.z, v.w);
    uint2 u;
    u.x = *reinterpret_cast<unsigned*>(&a);
    u.y = *reinterpret_cast<unsigned*>(&b);
    *reinterpret_cast<uint2*>(dst) = u;
}

// ---------------- CSR build ----------------
__global__ void count_k(const int* __restrict__ ei, int E) {
    if (blockIdx.x == 0 && threadIdx.x < 64) d_stat[threadIdx.x] = 0u;
    int e = blockIdx.x * blockDim.x + threadIdx.x;
    if (e < E) atomicAdd(&d_cnt[ei[E + e]], 1);
}

// single-pass scan with decoupled lookback (grid <= 64 blocks, single wave)
__global__ void scan_fused(int n, int E) {
    cudaGridDependencySynchronize();   // wait for count_k's d_cnt
    __shared__ int wsum[32];
    __shared__ int s_prev;
    int tid = threadIdx.x, lane = tid & 31, w = tid >> 5;
    int i = blockIdx.x * 1024 + tid;
    int v = (i < n) ? d_cnt[i] : 0;
    int x = v;
    #pragma unroll
    for (int o = 1; o < 32; o <<= 1) {
        int t = __shfl_up_sync(~0u, x, o);
        if (lane >= o) x += t;
    }
    if (lane == 31) wsum[w] = x;
    __syncthreads();
    if (w == 0) {
        int y = wsum[lane];
        #pragma unroll
        for (int o = 1; o < 32; o <<= 1) {
            int t = __shfl_up_sync(~0u, y, o);
            if (lane >= o) y += t;
        }
        wsum[lane] = y;
    }
    __syncthreads();
    int incl = x + (w > 0 ? wsum[w - 1] : 0);
    unsigned total = (unsigned)wsum[31];

    if (tid == 0) {
        int bid = blockIdx.x;
        if (bid == 0) {
            atomicExch(&d_stat[0], (2u << 30) | total);
            s_prev = 0;
        } else {
            atomicExch(&d_stat[bid], (1u << 30) | total);
            unsigned prev = 0;
            for (int j = bid - 1; j >= 0; j--) {
                unsigned st;
                do { st = atomicAdd(&d_stat[j], 0u); } while ((st >> 30) == 0u);
                prev += st & 0x3FFFFFFFu;
                if ((st >> 30) == 2u) break;
            }
            atomicExch(&d_stat[bid], (2u << 30) | (prev + total));
            s_prev = (int)prev;
        }
    }
    __syncthreads();
    int base = s_prev;
    if (i < n) {
        int val = incl - v + base;
        d_rp[i] = val;
        d_cur[i] = val;
    }
    if (i == 0) d_rp[n] = E;
}

// scatter into packed CSR (ONE 16B store per edge); re-zero d_cnt for next replay
__global__ void scatter_zero(const int* __restrict__ ei, const float* __restrict__ eattr,
                             int E, int n) {
    int e = blockIdx.x * blockDim.x + threadIdx.x;
    int src = 0, dst = 0; float at = 0.f;
    if (e < E) {
        src = ei[e];
        dst = ei[E + e];
        at = eattr[e];
    }
    cudaGridDependencySynchronize();   // wait for scan's d_cur
    if (e < n) d_cnt[e] = 0;
    if (e < E) {
        int pos = atomicAdd(&d_cur[dst], 1);
        int4 val;
        val.x = src;
        val.y = e;
        val.z = __float_as_int(at);
        val.w = 0;
        d_pk[pos] = val;
    }
}

// ---------------- register-blocked GEMM (sX[64][65]); fp16 output to d_tmpH ----------------
template <bool DEP_SYNC>
__device__ __forceinline__ void gemm64r_att_body(const float* __restrict__ X,
                                                 const float* __restrict__ W,
                                                 const float* __restrict__ attl,
                                                 const float* __restrict__ attr_, int n) {
    __shared__ float sX[64][65];
    __shared__ float sW[64 * 64];
    int tid = threadIdx.x;  // 256
    int row0 = blockIdx.x * 64;
    #pragma unroll
    for (int i = 0; i < 4; i++)
        ((float4*)sW)[tid + 256 * i] = ((const float4*)W)[tid + 256 * i];
    if (DEP_SYNC) cudaGridDependencySynchronize();
    #pragma unroll
    for (int i = 0; i < 4; i++) {
        int idx = tid + 256 * i;
        int r = idx >> 4, c4 = (idx & 15) * 4;
        int gr = row0 + r;
        float4 xv = (gr < n) ? *(const float4*)&X[gr * 64 + c4]
                             : make_float4(0.f, 0.f, 0.f, 0.f);
        sX[r][c4] = xv.x; sX[r][c4 + 1] = xv.y; sX[r][c4 + 2] = xv.z; sX[r][c4 + 3] = xv.w;
    }
    __syncthreads();
    int tx = tid & 15, ty = tid >> 4;
    int rb = ty * 4, cb = tx * 4;
    float4 ac[4] = {{0,0,0,0},{0,0,0,0},{0,0,0,0},{0,0,0,0}};
    #pragma unroll
    for (int k = 0; k < 64; k++) {
        float4 wv = *(const float4*)&sW[k * 64 + cb];
        float x0 = sX[rb][k], x1 = sX[rb + 1][k], x2 = sX[rb + 2][k], x3 = sX[rb + 3][k];
        ac[0].x += x0 * wv.x; ac[0].y += x0 * wv.y; ac[0].z += x0 * wv.z; ac[0].w += x0 * wv.w;
        ac[1].x += x1 * wv.x; ac[1].y += x1 * wv.y; ac[1].z += x1 * wv.z; ac[1].w += x1 * wv.w;
        ac[2].x += x2 * wv.x; ac[2].y += x2 * wv.y; ac[2].z += x2 * wv.z; ac[2].w += x2 * wv.w;
        ac[3].x += x3 * wv.x; ac[3].y += x3 * wv.y; ac[3].z += x3 * wv.z; ac[3].w += x3 * wv.w;
    }
    float4 l4 = *(const float4*)&attl[cb];
    float4 r4 = *(const float4*)&attr_[cb];
    float la[4], ra[4], pp[4];
    #pragma unroll
    for (int i = 0; i < 4; i++) {
        la[i] = ac[i].x * l4.x + ac[i].y * l4.y + ac[i].z * l4.z + ac[i].w * l4.w;
        ra[i] = ac[i].x * r4.x + ac[i].y * r4.y + ac[i].z * r4.z + ac[i].w * r4.w;
        pp[i] = ac[i].x * ac[i].x + ac[i].y * ac[i].y + ac[i].z * ac[i].z + ac[i].w * ac[i].w;
    }
    #pragma unroll
    for (int o = 8; o; o >>= 1) {
        #pragma unroll
        for (int i = 0; i < 4; i++) {
            la[i] += __shfl_xor_sync(~0u, la[i], o);
            ra[i] += __shfl_xor_sync(~0u, ra[i], o);
            pp[i] += __shfl_xor_sync(~0u, pp[i], o);
        }
    }
    #pragma unroll
    for (int i = 0; i < 4; i++) {
        int gr = row0 + rb + i;
        if (gr < n) {
            st_half4(&d_tmpH[gr * 64 + cb], ac[i]);
            if (tx == 0) { d_al[gr] = la[i]; d_ar[gr] = ra[i]; d_p[gr] = pp[i]; }
        }
    }
}

__global__ void gemm64r_att_x(const float* __restrict__ X, const float* __restrict__ W,
                              const float* __restrict__ attl, const float* __restrict__ attr_, int n) {
    gemm64r_att_body<false>(X, W, attl, attr_, n);
}
__global__ void gemm64r_att_h(const float* __restrict__ W,
                              const float* __restrict__ attl, const float* __restrict__ attr_, int n) {
    gemm64r_att_body<true>(d_h, W, attl, attr_, n);
}

// fused: A = h@W_top -> d_tmpH, B = h@W_bot -> d_BH (fp16 outputs)
__global__ void gemm64r_mlp2(const float* __restrict__ Wtop, const float* __restrict__ Wbot, int n) {
    __shared__ float sX[64][65];
    __shared__ float sW1[64 * 64];
    __shared__ float sW2[64 * 64];
    int tid = threadIdx.x;
    int row0 = blockIdx.x * 64;
    #pragma unroll
    for (int i = 0; i < 4; i++) {
        ((float4*)sW1)[tid + 256 * i] = ((const float4*)Wtop)[tid + 256 * i];
        ((float4*)sW2)[tid + 256 * i] = ((const float4*)Wbot)[tid + 256 * i];
    }
    cudaGridDependencySynchronize();   // wait for agg2's d_h
    #pragma unroll
    for (int i = 0; i < 4; i++) {
        int idx = tid + 256 * i;
        int r = idx >> 4, c4 = (idx & 15) * 4;
        int gr = row0 + r;
        float4 xv = (gr < n) ? *(const float4*)&d_h[gr * 64 + c4]
                             : make_float4(0.f, 0.f, 0.f, 0.f);
        sX[r][c4] = xv.x; sX[r][c4 + 1] = xv.y; sX[r][c4 + 2] = xv.z; sX[r][c4 + 3] = xv.w;
    }
    __syncthreads();
    int tx = tid & 15, ty = tid >> 4;
    int rb = ty * 4, cb = tx * 4;
    float4 a[4] = {{0,0,0,0},{0,0,0,0},{0,0,0,0},{0,0,0,0}};
    float4 b[4] = {{0,0,0,0},{0,0,0,0},{0,0,0,0},{0,0,0,0}};
    #pragma unroll
    for (int k = 0; k < 64; k++) {
        float4 w1 = *(const float4*)&sW1[k * 64 + cb];
        float4 w2 = *(const float4*)&sW2[k * 64 + cb];
        float x0 = sX[rb][k], x1 = sX[rb + 1][k], x2 = sX[rb + 2][k], x3 = sX[rb + 3][k];
        a[0].x += x0 * w1.x; a[0].y += x0 * w1.y; a[0].z += x0 * w1.z; a[0].w += x0 * w1.w;
        a[1].x += x1 * w1.x; a[1].y += x1 * w1.y; a[1].z += x1 * w1.z; a[1].w += x1 * w1.w;
        a[2].x += x2 * w1.x; a[2].y += x2 * w1.y; a[2].z += x2 * w1.z; a[2].w += x2 * w1.w;
        a[3].x += x3 * w1.x; a[3].y += x3 * w1.y; a[3].z += x3 * w1.z; a[3].w += x3 * w1.w;
        b[0].x += x0 * w2.x; b[0].y += x0 * w2.y; b[0].z += x0 * w2.z; b[0].w += x0 * w2.w;
        b[1].x += x1 * w2.x; b[1].y += x1 * w2.y; b[1].z += x1 * w2.z; b[1].w += x1 * w2.w;
        b[2].x += x2 * w2.x; b[2].y += x2 * w2.y; b[2].z += x2 * w2.z; b[2].w += x2 * w2.w;
        b[3].x += x3 * w2.x; b[3].y += x3 * w2.y; b[3].z += x3 * w2.z; b[3].w += x3 * w2.w;
    }
    #pragma unroll
    for (int i = 0; i < 4; i++) {
        int gr = row0 + rb + i;
        if (gr < n) {
            st_half4(&d_tmpH[gr * 64 + cb], a[i]);
            st_half4(&d_BH[gr * 64 + cb], b[i]);
        }
    }
}

// sigmoid via MUFU.TANH
__device__ __forceinline__ float lrelu_sig(float base, float q) {
    float t;
    asm("tanh.approx.f32 %0, %1;" : "=f"(t) : "f"(q * 0.5f));
    float a = base * (0.5f * t + 0.5f);
    return fmaxf(a, 0.2f * a);
}

// ---------------- half-warp aggregation, direct exp-sum, fp16 gathers ----------------
__global__ void aggregate2(const float* __restrict__ bias, int n) {
    int lane = threadIdx.x & 31;
    int half = lane >> 4, l = lane & 15;
    float4 bv = ((const float4*)bias)[l];
    cudaGridDependencySynchronize();
    int gw = (blockIdx.x * blockDim.x + threadIdx.x) >> 5;
    int node = gw * 2 + half;
    if (node >= n) return;
    unsigned mk = 0xFFFFu << (half * 16);
    const uint2* hp = (const uint2*)d_tmpH;
    float4 hd = ld_half4(hp, node * 16 + l);
    float ar_i = d_ar[node];

    float e_self = __expf(lrelu_sig(d_al[node] + ar_i, d_p[node]));
    float s = e_self;
    float4 acc = make_float4(e_self * hd.x, e_self * hd.y, e_self * hd.z, e_self * hd.w);

    int beg = d_rp[node], end = d_rp[node + 1];
    for (int k = beg; k < end; k += 8) {
        int id[8];
        float4 v[8];
        float q[8];
        #pragma unroll
        for (int i = 0; i < 8; i++) id[i] = (k + i < end) ? d_pk[k + i].x : d_pk[k].x;
        #pragma unroll
        for (int i = 0; i < 8; i++) v[i] = ld_half4(hp, id[i] * 16 + l);
        #pragma unroll
        for (int i = 0; i < 8; i++)
            q[i] = hd.x * v[i].x + hd.y * v[i].y + hd.z * v[i].z + hd.w * v[i].w;
        #pragma unroll
        for (int o = 8; o; o >>= 1) {
            #pragma unroll
            for (int i = 0; i < 8; i++) q[i] += __shfl_xor_sync(mk, q[i], o);
        }
        #pragma unroll
        for (int i = 0; i < 8; i++) {
            float e = (k + i < end) ? __expf(lrelu_sig(d_al[id[i]] + ar_i, q[i])) : 0.f;
            s += e;
            acc.x += e * v[i].x; acc.y += e * v[i].y;
            acc.z += e * v[i].z; acc.w += e * v[i].w;
        }
    }
    float inv = __fdividef(1.f, s);
    float4 o;
    o.x = fmaxf(acc.x * inv + bv.x, 0.f);
    o.y = fmaxf(acc.y * inv + bv.y, 0.f);
    o.z = fmaxf(acc.z * inv + bv.z, 0.f);
    o.w = fmaxf(acc.w * inv + bv.w, 0.f);
    ((float4*)d_h)[node * 16 + l] = o;
}

// ---------------- edge MLP, CSR-grouped, half-warp, batch 8, fp16 gathers ----------------
__global__ void edge_mlp2(const float* __restrict__ Wm1, const float* __restrict__ bm1,
                          const float* __restrict__ Wm2, const float* __restrict__ bm2,
                          float* __restrict__ out, int n) {
    int lane = threadIdx.x & 31;
    int half = lane >> 4, l = lane & 15;
    float4 we = ((const float4*)(Wm1 + 64 * 64))[l];  // row 64 of [129,64]
    float4 bb = ((const float4*)bm1)[l];
    float4 w2 = ((const float4*)Wm2)[l];
    float b2c = bm2[0];
    cudaGridDependencySynchronize();
    int gw = (blockIdx.x * blockDim.x + threadIdx.x) >> 5;
    int node = gw * 2 + half;
    if (node >= n) return;
    unsigned mk = 0xFFFFu << (half * 16);
    const uint2* Ap = (const uint2*)d_tmpH;
    const uint2* Bp = (const uint2*)d_BH;
    float4 bd = ld_half4(Bp, node * 16 + l);
    bd.x += bb.x; bd.y += bb.y; bd.z += bb.z; bd.w += bb.w;

    int beg = d_rp[node], end = d_rp[node + 1];
    for (int k = beg; k < end; k += 8) {
        int id[8], eo[8];
        float t[8], p[8];
        #pragma unroll
        for (int i = 0; i < 8; i++) {
            bool ok = (k + i < end);
            int4 pk = ok ? d_pk[k + i] : d_pk[k];
            id[i] = pk.x;
            eo[i] = ok ? pk.y : -1;
            t[i]  = __int_as_float(pk.z);
        }
        #pragma unroll
        for (int i = 0; i < 8; i++) {
            float4 a = ld_half4(Ap, id[i] * 16 + l);
            float vx = fmaxf(a.x + bd.x + t[i] * we.x, 0.f);
            float vy = fmaxf(a.y + bd.y + t[i] * we.y, 0.f);
            float vz = fmaxf(a.z + bd.z + t[i] * we.z, 0.f);
            float vw = fmaxf(a.w + bd.w + t[i] * we.w, 0.f);
            p[i] = vx * w2.x + vy * w2.y + vz * w2.z + vw * w2.w;
        }
        #pragma unroll
        for (int o = 8; o; o >>= 1) {
            #pragma unroll
            for (int i = 0; i < 8; i++) p[i] += __shfl_xor_sync(mk, p[i], o);
        }
        if (l == 0) {
            #pragma unroll
            for (int i = 0; i < 8; i++)
                if (eo[i] >= 0) out[eo[i]] = p[i] + b2c;
        }
    }
}

// ---------------- launch helpers ----------------
template <typename F, typename... Args>
static inline void launch_pss(F kern, dim3 g, dim3 b, cudaStream_t s, Args... args) {
    cudaLaunchConfig_t cfg = {};
    cfg.gridDim = g;
    cfg.blockDim = b;
    cfg.dynamicSmemBytes = 0;
    cfg.stream = s;
    cudaLaunchAttribute attrs[1];
    attrs[0].id = cudaLaunchAttributeProgrammaticStreamSerialization;
    attrs[0].val.programmaticStreamSerializationAllowed = 1;
    cfg.attrs = attrs;
    cfg.numAttrs = 1;
    cudaLaunchKernelEx(&cfg, kern, args...);
}

// ---------------- launch ----------------
extern "C" void kernel_launch(void* const* d_in, const int* in_sizes, int n_in,
                              void* d_out, int out_size) {
    const float* x     = (const float*)d_in[0];
    const int*   ei    = (const int*)d_in[1];     // int32: JAX x64 disabled
    const float* eattr = (const float*)d_in[2];
    const float* W1    = (const float*)d_in[3];
    const float* attl1 = (const float*)d_in[4];
    const float* attr1 = (const float*)d_in[5];
    const float* b1    = (const float*)d_in[6];
    const float* W2    = (const float*)d_in[7];
    const float* attl2 = (const float*)d_in[8];
    const float* attr2 = (const float*)d_in[9];
    const float* b2    = (const float*)d_in[10];
    const float* Wm1   = (const float*)d_in[11];
    const float* bm1   = (const float*)d_in[12];
    const float* Wm2   = (const float*)d_in[13];
    const float* bm2   = (const float*)d_in[14];
    float* out = (float*)d_out;

    int N = in_sizes[0] / C;
    int E = in_sizes[2];

    int eb = (E + 255) / 256;
    int gb = (N + 63) / 64;
    int npairs = (N + 1) / 2;
    int pb = (npairs * 32 + 255) / 256;
    int sb = (N + 1023) / 1024;   // <= 64 for the lookback scan

    // side stream: overlap layer-1 GEMM (inputs only) with the CSR build
    static cudaStream_t s2 = nullptr;
    static cudaEvent_t ev_fork = nullptr, ev_join = nullptr;
    if (s2 == nullptr) {
        cudaStreamCreateWithFlags(&s2, cudaStreamNonBlocking);
        cudaEventCreateWithFlags(&ev_fork, cudaEventDisableTiming);
        cudaEventCreateWithFlags(&ev_join, cudaEventDisableTiming);
    }

    cudaEventRecord(ev_fork, 0);
    cudaStreamWaitEvent(s2, ev_fork, 0);
    gemm64r_att_x<<<gb, 256, 0, s2>>>(x, W1, attl1, attr1, N);
    cudaEventRecord(ev_join, s2);

    // CSR build on main stream (PDL-chained)
    count_k<<<eb, 256>>>(ei, E);
    launch_pss(scan_fused, dim3(sb), dim3(1024), (cudaStream_t)0, N, E);
    launch_pss(scatter_zero, dim3(eb), dim3(256), (cudaStream_t)0, ei, eattr, E, N);

    // join, then layer 1 aggregation
    cudaStreamWaitEvent(0, ev_join, 0);
    launch_pss(aggregate2, dim3(pb), dim3(256), (cudaStream_t)0, b1, N);

    // layer 2
    launch_pss(gemm64r_att_h, dim3(gb), dim3(256), (cudaStream_t)0, W2, attl2, attr2, N);
    launch_pss(aggregate2, dim3(pb), dim3(256), (cudaStream_t)0, b2, N);

    // edge MLP
    launch_pss(gemm64r_mlp2, dim3(gb), dim3(256), (cudaStream_t)0, Wm1, Wm1 + 65 * 64, N);
    launch_pss(edge_mlp2, dim3(pb), dim3(256), (cudaStream_t)0, Wm1, bm1, Wm2, bm2, out, N);
}